// round 6
// baseline (speedup 1.0000x reference)
#include <cuda_runtime.h>
#include <cuda_bf16.h>
#include <cstdint>

#define T_DIM 512
#define B_DIM 128
#define E_DIM 256
#define U_DIM 256

// Scratch for xW[t][b][u]  (64 MB fp32 — L2-resident)
__device__ float g_xw[T_DIM * B_DIM * U_DIM];

// ---------------- helpers ----------------
__device__ __forceinline__ uint32_t smem_u32(const void* p) {
    uint32_t a;
    asm("{ .reg .u64 t; cvta.to.shared.u64 t, %1; cvt.u32.u64 %0, t; }" : "=r"(a) : "l"(p));
    return a;
}
__device__ __forceinline__ uint32_t packbf(float a, float b) {
    __nv_bfloat162 t = __floats2bfloat162_rn(a, b);   // .x -> low 16, .y -> high 16
    return *reinterpret_cast<uint32_t*>(&t);
}
__device__ __forceinline__ float blo(uint32_t v) { return __uint_as_float(v << 16); }

__device__ __forceinline__ void ldsm_x4(uint32_t* r, uint32_t addr) {
    asm volatile("ldmatrix.sync.aligned.m8n8.x4.shared.b16 {%0,%1,%2,%3}, [%4];"
                 : "=r"(r[0]), "=r"(r[1]), "=r"(r[2]), "=r"(r[3]) : "r"(addr));
}
__device__ __forceinline__ void ldsm_x2(uint32_t* r, uint32_t addr) {
    asm volatile("ldmatrix.sync.aligned.m8n8.x2.shared.b16 {%0,%1}, [%2];"
                 : "=r"(r[0]), "=r"(r[1]) : "r"(addr));
}
__device__ __forceinline__ void mma_bf16(float* c, const uint32_t* a, const uint32_t* b) {
    asm volatile("mma.sync.aligned.m16n8k16.row.col.f32.bf16.bf16.f32 "
                 "{%0,%1,%2,%3}, {%4,%5,%6,%7}, {%8,%9}, {%0,%1,%2,%3};"
                 : "+f"(c[0]), "+f"(c[1]), "+f"(c[2]), "+f"(c[3])
                 : "r"(a[0]), "r"(a[1]), "r"(a[2]), "r"(a[3]), "r"(b[0]), "r"(b[1]));
}

// ---------------- Kernel 1: xW[t][b][u] = emb[token(b,t)] . W[u] ----------------
// One CTA per timestep t (512 CTAs, 256 threads / 8 warps), bf16 HMMA.

static constexpr int APAD = 264;                     // bf16 elems per smem row
static constexpr int AS_OFF = 0;
static constexpr int BS_OFF = 128 * APAD * 2;        // 67584
static constexpr int XW_SMEM = BS_OFF + 256 * APAD * 2;  // 202752

__global__ void __launch_bounds__(256, 1)
xw_kernel(const int* __restrict__ sentence, const float* __restrict__ emb,
          const float* __restrict__ W) {
    extern __shared__ char smem[];
    const int tid = threadIdx.x, t = blockIdx.x;
    const int wid = tid >> 5, lane = tid & 31;
    const uint32_t sb = smem_u32(smem);

    // stage A (emb rows of this timestep's tokens)
    {
        const int sub = tid & 7;
        #pragma unroll
        for (int p = 0; p < 4; p++) {
            const int r = p * 32 + (tid >> 3);
            const int tok = sentence[r * T_DIM + t];
            const float4* src = reinterpret_cast<const float4*>(emb + (size_t)tok * E_DIM) + sub;
            char* dstrow = smem + AS_OFF + r * (APAD * 2);
            #pragma unroll
            for (int j = 0; j < 8; j++) {
                float4 v = src[j * 8];
                *reinterpret_cast<uint2*>(dstrow + (sub + j * 8) * 8) =
                    make_uint2(packbf(v.x, v.y), packbf(v.z, v.w));
            }
        }
    }
    // stage B (W rows)
    {
        const int sub = tid & 7;
        #pragma unroll
        for (int p = 0; p < 8; p++) {
            const int r = p * 32 + (tid >> 3);
            const float4* src = reinterpret_cast<const float4*>(W + (size_t)r * E_DIM) + sub;
            char* dstrow = smem + BS_OFF + r * (APAD * 2);
            #pragma unroll
            for (int j = 0; j < 8; j++) {
                float4 v = src[j * 8];
                *reinterpret_cast<uint2*>(dstrow + (sub + j * 8) * 8) =
                    make_uint2(packbf(v.x, v.y), packbf(v.z, v.w));
            }
        }
    }
    __syncthreads();

    const int m0 = wid * 16;
    float c[32][4];
    #pragma unroll
    for (int j = 0; j < 32; j++) { c[j][0] = c[j][1] = c[j][2] = c[j][3] = 0.f; }

    const uint32_t a_addr = sb + AS_OFF + (m0 + (lane & 15)) * (APAD * 2) + (lane >> 4) * 16;
    const uint32_t b_addr = sb + BS_OFF + (lane & 7) * (APAD * 2) + ((lane >> 3) & 1) * 16;

    for (int k = 0; k < 16; k++) {
        uint32_t a[4];
        ldsm_x4(a, a_addr + k * 32);
        #pragma unroll
        for (int j = 0; j < 32; j++) {
            uint32_t b[2];
            ldsm_x2(b, b_addr + j * 8 * (APAD * 2) + k * 32);
            mma_bf16(c[j], a, b);
        }
    }

    float* outp = g_xw + (size_t)t * (B_DIM * U_DIM);
    const int r0 = m0 + (lane >> 2), c0 = (lane & 3) * 2;
    #pragma unroll
    for (int j = 0; j < 32; j++) {
        const int col = j * 8 + c0;
        *reinterpret_cast<float2*>(outp + r0 * U_DIM + col)       = make_float2(c[j][0], c[j][1]);
        *reinterpret_cast<float2*>(outp + (r0 + 8) * U_DIM + col) = make_float2(c[j][2], c[j][3]);
    }
}

// ---------------- Kernel 2: recurrence + head ----------------
// 128 CTAs, 1024 threads. u = tid>>2, p = tid&3 (4 threads per unit).
// Thread (u,p) owns k-chunks c = 4i+p (i=0..15), 4 k per chunk: U as 32 bf16x2 regs.
// h double-buffered fp32 in smem; 4-way reduce via 2 shfl.bfly; xw prefetched 1 step ahead.

__global__ void __launch_bounds__(1024, 1)
rnn_kernel(const float* __restrict__ Um, const float* __restrict__ W1,
           const float* __restrict__ b1, const float* __restrict__ W2,
           const float* __restrict__ b2, float* __restrict__ out) {
    __shared__ float h[512 + 32];
    float* hid = h + 512;
    const int tid = threadIdx.x;
    const int b   = blockIdx.x;
    const int u   = tid >> 2;
    const int p   = tid & 3;

    // one-time: U row u, chunks c = 4i+p -> 32 bf16x2 regs
    uint32_t ur[32];
    {
        const float4* src = reinterpret_cast<const float4*>(Um + (size_t)u * U_DIM);
        #pragma unroll
        for (int i = 0; i < 16; i++) {
            float4 v = src[4 * i + p];
            ur[2 * i]     = packbf(v.x, v.y);
            ur[2 * i + 1] = packbf(v.z, v.w);
        }
    }
    if (tid < 256) h[tid] = 0.0f;   // buffer 0 = initial state
    __syncthreads();

    const float* xwb = g_xw + (size_t)b * U_DIM + u;   // stride per t: B*U floats
    float xw = xwb[0];

    #pragma unroll 2
    for (int t = 0; t < T_DIM; t++) {
        const int tn = (t + 1 < T_DIM) ? t + 1 : t;
        const float xw_n = xwb[(size_t)tn * (B_DIM * U_DIM)];  // prefetch next step
        const float4* hp = reinterpret_cast<const float4*>(h + ((t & 1) << 8)) + p;
        float a0 = 0.f, a1 = 0.f, a2 = 0.f, a3 = 0.f;
        #pragma unroll
        for (int i = 0; i < 16; i++) {
            float4 hv = hp[4 * i];                 // chunk 4i+p (16B, 4 distinct/quad)
            const uint32_t r0 = ur[2 * i], r1 = ur[2 * i + 1];
            a0 = fmaf(blo(r0), hv.x, a0);
            a1 = fmaf(__uint_as_float(r0), hv.y, a1);   // hi bf16, dirty mantissa
            a2 = fmaf(blo(r1), hv.z, a2);
            a3 = fmaf(__uint_as_float(r1), hv.w, a3);
        }
        float s = (a0 + a1) + (a2 + a3);
        s += __shfl_xor_sync(0xffffffffu, s, 1);
        s += __shfl_xor_sync(0xffffffffu, s, 2);
        s += xw;
        float hn;
        asm("tanh.approx.f32 %0, %1;" : "=f"(hn) : "f"(s));
        if (p == 0) h[(((t & 1) ^ 1) << 8) + u] = hn;
        xw = xw_n;
        __syncthreads();
    }

    // Head: final h in buffer 0 (t=511 wrote buffer 0)
    const float* hf = h;
    if (tid < 32) {
        float a = b1[tid];
        #pragma unroll 8
        for (int k = 0; k < 256; k++) a += hf[k] * W1[k * 32 + tid];
        hid[tid] = fmaxf(a, 0.0f);
    }
    __syncthreads();
    if (tid == 0) {
        float l0 = b2[0], l1 = b2[1];
        #pragma unroll
        for (int j = 0; j < 32; j++) {
            float x = hid[j];
            l0 += x * W2[j * 2 + 0];
            l1 += x * W2[j * 2 + 1];
        }
        float mx = fmaxf(l0, l1);
        float e0 = __expf(l0 - mx), e1 = __expf(l1 - mx);
        float inv = 1.0f / (e0 + e1);
        out[b * 2 + 0] = e0 * inv;
        out[b * 2 + 1] = e1 * inv;
    }
}

// ---------------- launch ----------------
extern "C" void kernel_launch(void* const* d_in, const int* in_sizes, int n_in,
                              void* d_out, int out_size) {
    const int*   sentence = (const int*)  d_in[0];
    const float* emb      = (const float*)d_in[1];
    const float* W        = (const float*)d_in[2];
    const float* Um       = (const float*)d_in[3];
    const float* W1       = (const float*)d_in[4];
    const float* b1       = (const float*)d_in[5];
    const float* W2       = (const float*)d_in[6];
    const float* b2       = (const float*)d_in[7];
    float* out = (float*)d_out;

    cudaFuncSetAttribute(xw_kernel, cudaFuncAttributeMaxDynamicSharedMemorySize, XW_SMEM);

    xw_kernel<<<T_DIM, 256, XW_SMEM>>>(sentence, emb, W);
    rnn_kernel<<<B_DIM, 1024>>>(Um, W1, b1, W2, b2, out);
}

// round 7
// speedup vs baseline: 1.0367x; 1.0367x over previous
#include <cuda_runtime.h>
#include <cuda_bf16.h>
#include <cstdint>

#define T_DIM 512
#define B_DIM 128
#define E_DIM 256
#define U_DIM 256

// Scratch for xW[t][b][u]  (64 MB fp32 — L2-resident)
__device__ float g_xw[T_DIM * B_DIM * U_DIM];

// ---------------- helpers ----------------
__device__ __forceinline__ uint32_t smem_u32(const void* p) {
    uint32_t a;
    asm("{ .reg .u64 t; cvta.to.shared.u64 t, %1; cvt.u32.u64 %0, t; }" : "=r"(a) : "l"(p));
    return a;
}
__device__ __forceinline__ uint32_t packbf(float a, float b) {
    __nv_bfloat162 t = __floats2bfloat162_rn(a, b);   // .x -> low 16, .y -> high 16
    return *reinterpret_cast<uint32_t*>(&t);
}
__device__ __forceinline__ float blo(uint32_t v) { return __uint_as_float(v << 16); }

__device__ __forceinline__ void ldsm_x4(uint32_t* r, uint32_t addr) {
    asm volatile("ldmatrix.sync.aligned.m8n8.x4.shared.b16 {%0,%1,%2,%3}, [%4];"
                 : "=r"(r[0]), "=r"(r[1]), "=r"(r[2]), "=r"(r[3]) : "r"(addr));
}
__device__ __forceinline__ void ldsm_x2(uint32_t* r, uint32_t addr) {
    asm volatile("ldmatrix.sync.aligned.m8n8.x2.shared.b16 {%0,%1}, [%2];"
                 : "=r"(r[0]), "=r"(r[1]) : "r"(addr));
}
__device__ __forceinline__ void mma_bf16(float* c, const uint32_t* a, const uint32_t* b) {
    asm volatile("mma.sync.aligned.m16n8k16.row.col.f32.bf16.bf16.f32 "
                 "{%0,%1,%2,%3}, {%4,%5,%6,%7}, {%8,%9}, {%0,%1,%2,%3};"
                 : "+f"(c[0]), "+f"(c[1]), "+f"(c[2]), "+f"(c[3])
                 : "r"(a[0]), "r"(a[1]), "r"(a[2]), "r"(a[3]), "r"(b[0]), "r"(b[1]));
}

// ---------------- Kernel 1: xW[t][b][u] = emb[token(b,t)] . W[u] ----------------
// One CTA per timestep t (512 CTAs, 256 threads / 8 warps), bf16 HMMA.

static constexpr int APAD = 264;                     // bf16 elems per smem row
static constexpr int AS_OFF = 0;
static constexpr int BS_OFF = 128 * APAD * 2;        // 67584
static constexpr int XW_SMEM = BS_OFF + 256 * APAD * 2;  // 202752

__global__ void __launch_bounds__(256, 1)
xw_kernel(const int* __restrict__ sentence, const float* __restrict__ emb,
          const float* __restrict__ W) {
    extern __shared__ char smem[];
    const int tid = threadIdx.x, t = blockIdx.x;
    const int wid = tid >> 5, lane = tid & 31;
    const uint32_t sb = smem_u32(smem);

    // stage A (emb rows of this timestep's tokens)
    {
        const int sub = tid & 7;
        #pragma unroll
        for (int p = 0; p < 4; p++) {
            const int r = p * 32 + (tid >> 3);
            const int tok = sentence[r * T_DIM + t];
            const float4* src = reinterpret_cast<const float4*>(emb + (size_t)tok * E_DIM) + sub;
            char* dstrow = smem + AS_OFF + r * (APAD * 2);
            #pragma unroll
            for (int j = 0; j < 8; j++) {
                float4 v = src[j * 8];
                *reinterpret_cast<uint2*>(dstrow + (sub + j * 8) * 8) =
                    make_uint2(packbf(v.x, v.y), packbf(v.z, v.w));
            }
        }
    }
    // stage B (W rows)
    {
        const int sub = tid & 7;
        #pragma unroll
        for (int p = 0; p < 8; p++) {
            const int r = p * 32 + (tid >> 3);
            const float4* src = reinterpret_cast<const float4*>(W + (size_t)r * E_DIM) + sub;
            char* dstrow = smem + BS_OFF + r * (APAD * 2);
            #pragma unroll
            for (int j = 0; j < 8; j++) {
                float4 v = src[j * 8];
                *reinterpret_cast<uint2*>(dstrow + (sub + j * 8) * 8) =
                    make_uint2(packbf(v.x, v.y), packbf(v.z, v.w));
            }
        }
    }
    __syncthreads();

    const int m0 = wid * 16;
    float c[32][4];
    #pragma unroll
    for (int j = 0; j < 32; j++) { c[j][0] = c[j][1] = c[j][2] = c[j][3] = 0.f; }

    const uint32_t a_addr = sb + AS_OFF + (m0 + (lane & 15)) * (APAD * 2) + (lane >> 4) * 16;
    const uint32_t b_addr = sb + BS_OFF + (lane & 7) * (APAD * 2) + ((lane >> 3) & 1) * 16;

    for (int k = 0; k < 16; k++) {
        uint32_t a[4];
        ldsm_x4(a, a_addr + k * 32);
        #pragma unroll
        for (int j = 0; j < 32; j++) {
            uint32_t b[2];
            ldsm_x2(b, b_addr + j * 8 * (APAD * 2) + k * 32);
            mma_bf16(c[j], a, b);
        }
    }

    float* outp = g_xw + (size_t)t * (B_DIM * U_DIM);
    const int r0 = m0 + (lane >> 2), c0 = (lane & 3) * 2;
    #pragma unroll
    for (int j = 0; j < 32; j++) {
        const int col = j * 8 + c0;
        *reinterpret_cast<float2*>(outp + r0 * U_DIM + col)       = make_float2(c[j][0], c[j][1]);
        *reinterpret_cast<float2*>(outp + (r0 + 8) * U_DIM + col) = make_float2(c[j][2], c[j][3]);
    }
}

// ---------------- Kernel 2: recurrence + head ----------------
// 128 CTAs, 1024 threads. u-group g = tid>>4 owns u in [4g,4g+4); k-part p = tid&15
// owns k-chunks 4*(p+16j), j=0..3. Each h float4 load feeds 4 outputs (4x reuse ->
// smem wavefront floor drops 2048 -> 512 cyc/step). U as 32 bf16x2 regs (dirty-hi).
// Reduce over 16 k-parts with 4 shfl.bfly rounds inside each half-warp.

__global__ void __launch_bounds__(1024, 1)
rnn_kernel(const float* __restrict__ Um, const float* __restrict__ W1,
           const float* __restrict__ b1, const float* __restrict__ W2,
           const float* __restrict__ b2, float* __restrict__ out) {
    __shared__ float h[512 + 32];
    float* hid = h + 512;
    const int tid = threadIdx.x;
    const int b   = blockIdx.x;
    const int g   = tid >> 4;        // u-group: u = 4g .. 4g+3
    const int p   = tid & 15;        // k-part

    // one-time: U rows 4g..4g+3, k-chunks 4*(p+16j) -> 32 bf16x2 regs
    uint32_t ur[32];                 // [uu*8 + j*2 + {0,1}]
    #pragma unroll
    for (int uu = 0; uu < 4; uu++) {
        const float4* src = reinterpret_cast<const float4*>(Um + (size_t)(4 * g + uu) * U_DIM);
        #pragma unroll
        for (int j = 0; j < 4; j++) {
            float4 v = src[p + 16 * j];
            ur[uu * 8 + j * 2]     = packbf(v.x, v.y);
            ur[uu * 8 + j * 2 + 1] = packbf(v.z, v.w);
        }
    }
    if (tid < 256) h[tid] = 0.0f;    // buffer 0 = initial state
    __syncthreads();

    // xw stream: lane p<4 handles u = 4g+p
    const float* xwp = g_xw + (size_t)b * U_DIM + 4 * g + p;
    float xw = (p < 4) ? xwp[0] : 0.0f;

    for (int t = 0; t < T_DIM; t++) {
        const int tn = (t + 1 < T_DIM) ? t + 1 : t;
        const float xw_n = (p < 4) ? xwp[(size_t)tn * (B_DIM * U_DIM)] : 0.0f;
        const float4* hb4 = reinterpret_cast<const float4*>(h + ((t & 1) << 8));

        float acc[4] = {0.f, 0.f, 0.f, 0.f};
        #pragma unroll
        for (int j = 0; j < 4; j++) {
            float4 hv = hb4[p + 16 * j];    // contiguous 256B across half-warp
            #pragma unroll
            for (int uu = 0; uu < 4; uu++) {
                const uint32_t r0 = ur[uu * 8 + j * 2], r1 = ur[uu * 8 + j * 2 + 1];
                acc[uu] = fmaf(blo(r0), hv.x, acc[uu]);
                acc[uu] = fmaf(__uint_as_float(r0), hv.y, acc[uu]);  // dirty-hi bf16
                acc[uu] = fmaf(blo(r1), hv.z, acc[uu]);
                acc[uu] = fmaf(__uint_as_float(r1), hv.w, acc[uu]);
            }
        }
        // reduce over 16 k-parts (stays within 16-lane half: xor bits 0..3)
        float s0 = acc[0], s1 = acc[1], s2 = acc[2], s3 = acc[3];
        #pragma unroll
        for (int m = 1; m <= 8; m <<= 1) {
            s0 += __shfl_xor_sync(0xffffffffu, s0, m);
            s1 += __shfl_xor_sync(0xffffffffu, s1, m);
            s2 += __shfl_xor_sync(0xffffffffu, s2, m);
            s3 += __shfl_xor_sync(0xffffffffu, s3, m);
        }
        if (p < 4) {
            float sv = (p == 0) ? s0 : (p == 1) ? s1 : (p == 2) ? s2 : s3;
            float r = sv + xw;
            float hn;
            asm("tanh.approx.f32 %0, %1;" : "=f"(hn) : "f"(r));
            h[(((t & 1) ^ 1) << 8) + 4 * g + p] = hn;
        }
        xw = xw_n;
        __syncthreads();
    }

    // Head: final h in buffer 0 (t=511 wrote buffer 0)
    const float* hf = h;
    if (tid < 32) {
        float a = b1[tid];
        #pragma unroll 8
        for (int k = 0; k < 256; k++) a += hf[k] * W1[k * 32 + tid];
        hid[tid] = fmaxf(a, 0.0f);
    }
    __syncthreads();
    if (tid == 0) {
        float l0 = b2[0], l1 = b2[1];
        #pragma unroll
        for (int j = 0; j < 32; j++) {
            float x = hid[j];
            l0 += x * W2[j * 2 + 0];
            l1 += x * W2[j * 2 + 1];
        }
        float mx = fmaxf(l0, l1);
        float e0 = __expf(l0 - mx), e1 = __expf(l1 - mx);
        float inv = 1.0f / (e0 + e1);
        out[b * 2 + 0] = e0 * inv;
        out[b * 2 + 1] = e1 * inv;
    }
}

// ---------------- launch ----------------
extern "C" void kernel_launch(void* const* d_in, const int* in_sizes, int n_in,
                              void* d_out, int out_size) {
    const int*   sentence = (const int*)  d_in[0];
    const float* emb      = (const float*)d_in[1];
    const float* W        = (const float*)d_in[2];
    const float* Um       = (const float*)d_in[3];
    const float* W1       = (const float*)d_in[4];
    const float* b1       = (const float*)d_in[5];
    const float* W2       = (const float*)d_in[6];
    const float* b2       = (const float*)d_in[7];
    float* out = (float*)d_out;

    cudaFuncSetAttribute(xw_kernel, cudaFuncAttributeMaxDynamicSharedMemorySize, XW_SMEM);

    xw_kernel<<<T_DIM, 256, XW_SMEM>>>(sentence, emb, W);
    rnn_kernel<<<B_DIM, 1024>>>(Um, W1, b1, W2, b2, out);
}